// round 1
// baseline (speedup 1.0000x reference)
#include <cuda_runtime.h>
#include <math.h>

#define Bq   8
#define Lseq 2048
#define Dk   300
#define Hk   150
#define NROWS (Bq*Lseq)     // 16384

// scratch (allocation-free rule -> __device__ globals)
__device__ float g_Qh[NROWS*Hk];
__device__ float g_P [NROWS*Hk];
__device__ float g_Ah[NROWS*Hk];

// ---------------------------------------------------------------------------
// Kernel 1: gated projection for Q and A rows; Q blocks also fuse P = Qh@Wg+bg
// grid.x = 1024 (first 512 blocks -> Q rows, next 512 -> A rows), 32 rows/block
// threads 256 as (tx=16, ty=16); thread computes 2 rows x 10 cols (n = tx+16j)
// ---------------------------------------------------------------------------
__global__ __launch_bounds__(256) void gate_kernel(
    const float* __restrict__ Q, const float* __restrict__ A,
    const float* __restrict__ Wi, const float* __restrict__ Wu,
    const float* __restrict__ Wg,
    const float* __restrict__ bi, const float* __restrict__ bu,
    const float* __restrict__ bg)
{
    // phase-overlapped shared union (42.24 KB static)
    __shared__ float sm[10560];
    float* Xs  = sm;          // [32][30]   gate phase
    float* Wis = sm + 960;    // [30][160]  gate phase
    float* Wus = sm + 5760;   // [30][160]  gate phase
    float* Qhs = sm;          // [32][160]  P phase (overlaps Xs+Wis)
    float* Wgs = sm + 5760;   // [30][160]  P phase (overlaps Wus)

    const int tid = threadIdx.x;
    const int tx = tid & 15, ty = tid >> 4;
    const bool isQ = (blockIdx.x < 512);
    const int row0 = (blockIdx.x & 511) * 32;
    const float* X = isQ ? Q : A;

    float ai[2][10], au[2][10];
    #pragma unroll
    for (int i = 0; i < 2; i++)
        #pragma unroll
        for (int j = 0; j < 10; j++) { ai[i][j] = 0.f; au[i][j] = 0.f; }

    for (int kt = 0; kt < 10; kt++) {
        for (int idx = tid; idx < 32*30; idx += 256) {
            int m = idx / 30, kk = idx - m*30;
            Xs[idx] = X[(size_t)(row0 + m) * Dk + kt*30 + kk];
        }
        for (int idx = tid; idx < 30*160; idx += 256) {
            int kk = idx / 160, n = idx - kk*160;
            float wi = 0.f, wu = 0.f;
            if (n < Hk) { int g = (kt*30 + kk) * Hk + n; wi = Wi[g]; wu = Wu[g]; }
            Wis[idx] = wi; Wus[idx] = wu;
        }
        __syncthreads();
        #pragma unroll 5
        for (int k = 0; k < 30; k++) {
            float x0 = Xs[(ty*2    )*30 + k];
            float x1 = Xs[(ty*2 + 1)*30 + k];
            #pragma unroll
            for (int j = 0; j < 10; j++) {
                float wi = Wis[k*160 + tx + 16*j];
                float wu = Wus[k*160 + tx + 16*j];
                ai[0][j] += x0 * wi; ai[1][j] += x1 * wi;
                au[0][j] += x0 * wu; au[1][j] += x1 * wu;
            }
        }
        __syncthreads();
    }

    // nonlinearity + store
    float hv[2][10];
    #pragma unroll
    for (int j = 0; j < 10; j++) {
        int n = tx + 16*j;
        float bib = (n < Hk) ? bi[n] : 0.f;
        float bub = (n < Hk) ? bu[n] : 0.f;
        #pragma unroll
        for (int i = 0; i < 2; i++) {
            float xi = ai[i][j] + bib;
            float xu = au[i][j] + bub;
            float s  = 1.f / (1.f + __expf(-xi));
            hv[i][j] = s * tanhf(xu);
        }
    }
    float* dst = isQ ? g_Qh : g_Ah;
    #pragma unroll
    for (int i = 0; i < 2; i++)
        #pragma unroll
        for (int j = 0; j < 10; j++) {
            int n = tx + 16*j;
            if (n < Hk) dst[(size_t)(row0 + ty*2 + i) * Hk + n] = hv[i][j];
        }

    if (!isQ) return;

    // ---- fused P = Qh @ Wg + bg for this 32-row tile ----
    __syncthreads();
    #pragma unroll
    for (int i = 0; i < 2; i++)
        #pragma unroll
        for (int j = 0; j < 10; j++)
            Qhs[(ty*2 + i)*160 + tx + 16*j] = hv[i][j];  // cols >=150 are 0, never read
    __syncthreads();

    float ap[2][10];
    #pragma unroll
    for (int i = 0; i < 2; i++)
        #pragma unroll
        for (int j = 0; j < 10; j++) ap[i][j] = 0.f;

    for (int kt = 0; kt < 5; kt++) {
        for (int idx = tid; idx < 30*160; idx += 256) {
            int kk = idx / 160, n = idx - kk*160;
            Wgs[idx] = (n < Hk) ? Wg[(kt*30 + kk) * Hk + n] : 0.f;
        }
        __syncthreads();
        #pragma unroll 5
        for (int k = 0; k < 30; k++) {
            float q0 = Qhs[(ty*2    )*160 + kt*30 + k];
            float q1 = Qhs[(ty*2 + 1)*160 + kt*30 + k];
            #pragma unroll
            for (int j = 0; j < 10; j++) {
                float wg = Wgs[k*160 + tx + 16*j];
                ap[0][j] += q0 * wg; ap[1][j] += q1 * wg;
            }
        }
        __syncthreads();
    }
    #pragma unroll
    for (int i = 0; i < 2; i++)
        #pragma unroll
        for (int j = 0; j < 10; j++) {
            int n = tx + 16*j;
            if (n < Hk) g_P[(size_t)(row0 + ty*2 + i) * Hk + n] = ap[i][j] + bg[n];
        }
}

// ---------------------------------------------------------------------------
// Kernel 2: flash attention over q (softmax axis) + fused relu-MLP epilogue
// grid (LA/64, B); 256 threads (16x16). Per thread: O[4 rows][10 h-lanes]
// ---------------------------------------------------------------------------
#define A_OFF   0
#define P_OFF   9792        // 64*153
#define QH_OFF  19584
#define S_OFF   29376       // Ss[64][65]
#define RM_OFF  33536
#define RL_OFF  33600
#define AL_OFF  33664
#define SMEM_ATTN_FLOATS 33728

__global__ __launch_bounds__(256) void attn_kernel(
    const float* __restrict__ Wt, const float* __restrict__ bt,
    float* __restrict__ out)
{
    extern __shared__ float sm[];
    float* Ahs  = sm + A_OFF;     // [64][153]
    float* Ps   = sm + P_OFF;     // [64][153]
    float* Qhs  = sm + QH_OFF;    // [64][153]
    float* Ss   = sm + S_OFF;     // [64][65]
    float* rowm = sm + RM_OFF;
    float* rowl = sm + RL_OFF;
    float* alph = sm + AL_OFF;

    const int tid = threadIdx.x;
    const int tx = tid & 15, ty = tid >> 4;
    const int b  = blockIdx.y;
    const int a0 = blockIdx.x * 64;
    const size_t base = (size_t)b * Lseq * Hk;

    for (int idx = tid; idx < 64*Hk; idx += 256) {
        int r = idx / Hk, c = idx - r*Hk;
        Ahs[r*153 + c] = g_Ah[base + (size_t)(a0 + r)*Hk + c];
    }
    if (tid < 64) { rowm[tid] = -INFINITY; rowl[tid] = 0.f; }

    float O[4][10];
    #pragma unroll
    for (int i = 0; i < 4; i++)
        #pragma unroll
        for (int j = 0; j < 10; j++) O[i][j] = 0.f;
    __syncthreads();

    for (int q0 = 0; q0 < Lseq; q0 += 64) {
        for (int idx = tid; idx < 64*Hk; idx += 256) {
            int r = idx / Hk, c = idx - r*Hk;
            size_t g = base + (size_t)(q0 + r)*Hk + c;
            Ps [r*153 + c] = g_P [g];
            Qhs[r*153 + c] = g_Qh[g];
        }
        __syncthreads();

        // S[a][q] = <Ah[a], P[q]>  (4x4 register tile, q = tx+16*jj)
        float s[4][4];
        #pragma unroll
        for (int i = 0; i < 4; i++)
            #pragma unroll
            for (int j = 0; j < 4; j++) s[i][j] = 0.f;
        for (int k = 0; k < Hk; k++) {
            float av[4], pv[4];
            #pragma unroll
            for (int i = 0; i < 4; i++) av[i] = Ahs[(ty*4 + i)*153 + k];
            #pragma unroll
            for (int j = 0; j < 4; j++) pv[j] = Ps [(tx + 16*j)*153 + k];
            #pragma unroll
            for (int i = 0; i < 4; i++)
                #pragma unroll
                for (int j = 0; j < 4; j++) s[i][j] += av[i] * pv[j];
        }
        #pragma unroll
        for (int i = 0; i < 4; i++)
            #pragma unroll
            for (int j = 0; j < 4; j++)
                Ss[(ty*4 + i)*65 + tx + 16*j] = s[i][j];
        __syncthreads();

        // online softmax over q (4 threads per a-row)
        {
            int row = tid >> 2, t4 = tid & 3;
            float mx = -INFINITY;
            #pragma unroll
            for (int q = 0; q < 16; q++) mx = fmaxf(mx, Ss[row*65 + t4*16 + q]);
            mx = fmaxf(mx, __shfl_xor_sync(0xffffffffu, mx, 1));
            mx = fmaxf(mx, __shfl_xor_sync(0xffffffffu, mx, 2));
            float mold = rowm[row];
            float mnew = fmaxf(mold, mx);
            float ssum = 0.f;
            #pragma unroll
            for (int q = 0; q < 16; q++) {
                float e = __expf(Ss[row*65 + t4*16 + q] - mnew);
                Ss[row*65 + t4*16 + q] = e;
                ssum += e;
            }
            ssum += __shfl_xor_sync(0xffffffffu, ssum, 1);
            ssum += __shfl_xor_sync(0xffffffffu, ssum, 2);
            if (t4 == 0) {
                float al = __expf(mold - mnew);
                alph[row] = al;
                rowl[row] = rowl[row] * al + ssum;
                rowm[row] = mnew;
            }
        }
        __syncthreads();

        // rescale O, accumulate O += E @ Qh
        float alr[4];
        #pragma unroll
        for (int i = 0; i < 4; i++) alr[i] = alph[ty*4 + i];
        #pragma unroll
        for (int i = 0; i < 4; i++)
            #pragma unroll
            for (int j = 0; j < 10; j++) O[i][j] *= alr[i];
        for (int q = 0; q < 64; q++) {
            float ev[4], qv[10];
            #pragma unroll
            for (int i = 0; i < 4; i++) ev[i] = Ss[(ty*4 + i)*65 + q];
            #pragma unroll
            for (int j = 0; j < 10; j++) qv[j] = Qhs[q*153 + tx + 16*j];
            #pragma unroll
            for (int i = 0; i < 4; i++)
                #pragma unroll
                for (int j = 0; j < 10; j++) O[i][j] += ev[i] * qv[j];
        }
        __syncthreads();
    }

    // normalize, stage Hm into Qhs buffer
    float linv[4];
    #pragma unroll
    for (int i = 0; i < 4; i++) linv[i] = 1.f / rowl[ty*4 + i];
    #pragma unroll
    for (int i = 0; i < 4; i++)
        #pragma unroll
        for (int j = 0; j < 10; j++) {
            int n = tx + 16*j;
            if (n < Hk) Qhs[(ty*4 + i)*153 + n] = O[i][j] * linv[i];
        }
    __syncthreads();

    // epilogue: T = relu([Ah, Hm] @ Wt + bt)
    float acc[4][10];
    #pragma unroll
    for (int j = 0; j < 10; j++) {
        int n = tx + 16*j;
        float bb = (n < Hk) ? bt[n] : 0.f;
        #pragma unroll
        for (int i = 0; i < 4; i++) acc[i][j] = bb;
    }
    for (int h = 0; h < Hk; h++) {
        float av[4], ov[4];
        #pragma unroll
        for (int i = 0; i < 4; i++) {
            av[i] = Ahs[(ty*4 + i)*153 + h];
            ov[i] = Qhs[(ty*4 + i)*153 + h];
        }
        #pragma unroll
        for (int j = 0; j < 10; j++) {
            int n = tx + 16*j;
            float w1 = (n < Hk) ? Wt[h*Hk + n]        : 0.f;
            float w2 = (n < Hk) ? Wt[(Hk + h)*Hk + n] : 0.f;
            #pragma unroll
            for (int i = 0; i < 4; i++) acc[i][j] += av[i]*w1 + ov[i]*w2;
        }
    }
    #pragma unroll
    for (int i = 0; i < 4; i++)
        #pragma unroll
        for (int j = 0; j < 10; j++) {
            int n = tx + 16*j;
            if (n < Hk)
                out[base + (size_t)(a0 + ty*4 + i)*Hk + n] = fmaxf(acc[i][j], 0.f);
        }
}

// ---------------------------------------------------------------------------
extern "C" void kernel_launch(void* const* d_in, const int* in_sizes, int n_in,
                              void* d_out, int out_size)
{
    const float* Q  = (const float*)d_in[0];
    const float* A  = (const float*)d_in[1];
    const float* Wi = (const float*)d_in[2];
    const float* Wu = (const float*)d_in[3];
    const float* Wg = (const float*)d_in[4];
    const float* Wt = (const float*)d_in[5];
    const float* bi = (const float*)d_in[6];
    const float* bu = (const float*)d_in[7];
    const float* bg = (const float*)d_in[8];
    const float* bt = (const float*)d_in[9];
    float* out = (float*)d_out;

    cudaFuncSetAttribute(attn_kernel,
                         cudaFuncAttributeMaxDynamicSharedMemorySize,
                         SMEM_ATTN_FLOATS * sizeof(float));

    gate_kernel<<<1024, 256>>>(Q, A, Wi, Wu, Wg, bi, bu, bg);
    attn_kernel<<<dim3(Lseq/64, Bq), 256, SMEM_ATTN_FLOATS * sizeof(float)>>>(Wt, bt, out);
}

// round 2
// speedup vs baseline: 1.1869x; 1.1869x over previous
#include <cuda_runtime.h>
#include <math.h>

#define Bq   8
#define Lseq 2048
#define Dk   300
#define Hk   150
#define NROWS (Bq*Lseq)     // 16384

// scratch (allocation-free rule -> __device__ globals)
__device__ float g_Qt[256*Hk*64];   // per 64-row q-tile, transposed [tile][h][q]
__device__ float g_P [NROWS*Hk];
__device__ float g_Ah[NROWS*Hk];

// ---------------- f32x2 helpers (Blackwell packed fp32) ----------------
typedef unsigned long long u64t;
__device__ __forceinline__ void ffma2(u64t &d, u64t a, u64t b) {
    asm("fma.rn.f32x2 %0, %1, %2, %0;" : "+l"(d) : "l"(a), "l"(b));
}
__device__ __forceinline__ u64t fmul2(u64t a, u64t b) {
    u64t d; asm("mul.rn.f32x2 %0, %1, %2;" : "=l"(d) : "l"(a), "l"(b)); return d;
}
__device__ __forceinline__ float lo_f(u64t v){ return __uint_as_float((unsigned)v); }
__device__ __forceinline__ float hi_f(u64t v){ return __uint_as_float((unsigned)(v>>32)); }
__device__ __forceinline__ u64t pack2(float x, float y){
    u64t d; asm("mov.b64 %0, {%1,%2};" : "=l"(d)
                : "r"(__float_as_uint(x)), "r"(__float_as_uint(y))); return d;
}

// ---------------------------------------------------------------------------
// Kernel 1: gated projection; Q blocks also fuse P = Qh@Wg+bg and write Qh
// TRANSPOSED per 64-row tile into g_Qt[tile][h][q%64].
// ---------------------------------------------------------------------------
__global__ __launch_bounds__(256) void gate_kernel(
    const float* __restrict__ Q, const float* __restrict__ A,
    const float* __restrict__ Wi, const float* __restrict__ Wu,
    const float* __restrict__ Wg,
    const float* __restrict__ bi, const float* __restrict__ bu,
    const float* __restrict__ bg)
{
    __shared__ float sm[10560];
    float* Xs  = sm;          // [32][30]
    float* Wis = sm + 960;    // [30][160]
    float* Wus = sm + 5760;   // [30][160]
    float* Qhs = sm;          // [32][160]  (P phase)
    float* Wgs = sm + 5760;   // [30][160]  (P phase)

    const int tid = threadIdx.x;
    const int tx = tid & 15, ty = tid >> 4;
    const bool isQ = (blockIdx.x < 512);
    const int row0 = (blockIdx.x & 511) * 32;
    const float* X = isQ ? Q : A;

    float ai[2][10], au[2][10];
    #pragma unroll
    for (int i = 0; i < 2; i++)
        #pragma unroll
        for (int j = 0; j < 10; j++) { ai[i][j] = 0.f; au[i][j] = 0.f; }

    for (int kt = 0; kt < 10; kt++) {
        for (int idx = tid; idx < 32*30; idx += 256) {
            int m = idx / 30, kk = idx - m*30;
            Xs[idx] = X[(size_t)(row0 + m) * Dk + kt*30 + kk];
        }
        for (int idx = tid; idx < 30*160; idx += 256) {
            int kk = idx / 160, n = idx - kk*160;
            float wi = 0.f, wu = 0.f;
            if (n < Hk) { int g = (kt*30 + kk) * Hk + n; wi = Wi[g]; wu = Wu[g]; }
            Wis[idx] = wi; Wus[idx] = wu;
        }
        __syncthreads();
        #pragma unroll 5
        for (int k = 0; k < 30; k++) {
            float x0 = Xs[(ty*2    )*30 + k];
            float x1 = Xs[(ty*2 + 1)*30 + k];
            #pragma unroll
            for (int j = 0; j < 10; j++) {
                float wi = Wis[k*160 + tx + 16*j];
                float wu = Wus[k*160 + tx + 16*j];
                ai[0][j] += x0 * wi; ai[1][j] += x1 * wi;
                au[0][j] += x0 * wu; au[1][j] += x1 * wu;
            }
        }
        __syncthreads();
    }

    float hv[2][10];
    #pragma unroll
    for (int j = 0; j < 10; j++) {
        int n = tx + 16*j;
        float bib = (n < Hk) ? bi[n] : 0.f;
        float bub = (n < Hk) ? bu[n] : 0.f;
        #pragma unroll
        for (int i = 0; i < 2; i++) {
            float xi = ai[i][j] + bib;
            float xu = au[i][j] + bub;
            float s  = 1.f / (1.f + __expf(-xi));
            hv[i][j] = s * tanhf(xu);
        }
    }

    if (isQ) {
        // transposed store: g_Qt[t64][n][q_in_64]
        int t64 = row0 >> 6;
        int qb  = row0 & 63;
        #pragma unroll
        for (int i = 0; i < 2; i++)
            #pragma unroll
            for (int j = 0; j < 10; j++) {
                int n = tx + 16*j;
                if (n < Hk)
                    g_Qt[((size_t)t64*Hk + n)*64 + qb + ty*2 + i] = hv[i][j];
            }
    } else {
        #pragma unroll
        for (int i = 0; i < 2; i++)
            #pragma unroll
            for (int j = 0; j < 10; j++) {
                int n = tx + 16*j;
                if (n < Hk) g_Ah[(size_t)(row0 + ty*2 + i) * Hk + n] = hv[i][j];
            }
        return;
    }

    // ---- fused P = Qh @ Wg + bg ----
    __syncthreads();
    #pragma unroll
    for (int i = 0; i < 2; i++)
        #pragma unroll
        for (int j = 0; j < 10; j++)
            Qhs[(ty*2 + i)*160 + tx + 16*j] = hv[i][j];
    __syncthreads();

    float ap[2][10];
    #pragma unroll
    for (int i = 0; i < 2; i++)
        #pragma unroll
        for (int j = 0; j < 10; j++) ap[i][j] = 0.f;

    for (int kt = 0; kt < 5; kt++) {
        for (int idx = tid; idx < 30*160; idx += 256) {
            int kk = idx / 160, n = idx - kk*160;
            Wgs[idx] = (n < Hk) ? Wg[(kt*30 + kk) * Hk + n] : 0.f;
        }
        __syncthreads();
        #pragma unroll 5
        for (int k = 0; k < 30; k++) {
            float q0 = Qhs[(ty*2    )*160 + kt*30 + k];
            float q1 = Qhs[(ty*2 + 1)*160 + kt*30 + k];
            #pragma unroll
            for (int j = 0; j < 10; j++) {
                float wg = Wgs[k*160 + tx + 16*j];
                ap[0][j] += q0 * wg; ap[1][j] += q1 * wg;
            }
        }
        __syncthreads();
    }
    #pragma unroll
    for (int i = 0; i < 2; i++)
        #pragma unroll
        for (int j = 0; j < 10; j++) {
            int n = tx + 16*j;
            if (n < Hk) g_P[(size_t)(row0 + ty*2 + i) * Hk + n] = ap[i][j] + bg[n];
        }
}

// ---------------------------------------------------------------------------
// Kernel 2: flash attention (softmax over q) with packed f32x2 math.
// smem: Ahs[64][154], Ps[64][154], Qt[160][70], Ss[64][66] + softmax state
// ---------------------------------------------------------------------------
#define A_OFF   0
#define P_OFF   9856
#define QT_OFF  19712
#define S_OFF   30912
#define RM_OFF  35136
#define RL_OFF  35200
#define AL_OFF  35264
#define SMEM_ATTN_FLOATS 35328

__global__ __launch_bounds__(256, 1) void attn_kernel(
    const float* __restrict__ Wt, const float* __restrict__ bt,
    float* __restrict__ out)
{
    extern __shared__ float sm[];
    float* Ahs  = sm + A_OFF;
    float* Ps   = sm + P_OFF;
    float* Qt   = sm + QT_OFF;
    float* Ss   = sm + S_OFF;
    float* rowm = sm + RM_OFF;
    float* rowl = sm + RL_OFF;
    float* alph = sm + AL_OFF;

    const int tid = threadIdx.x;
    const int tx = tid & 15, ty = tid >> 4;
    const int ty4 = ty * 4;
    const int b  = blockIdx.y;
    const int a0 = blockIdx.x * 64;
    const size_t base = (size_t)b * Lseq * Hk;

    // stage Ah tile (float2)
    for (int idx = tid; idx < 64*75; idx += 256) {
        int r = idx / 75, c = idx - r*75;
        *(float2*)&Ahs[r*154 + 2*c] =
            *(const float2*)&g_Ah[base + (size_t)(a0 + r)*Hk + 2*c];
    }
    // zero pad rows 150..159 of Qt (read by j=9 lanes with n>=150)
    for (int idx = tid; idx < 10*64; idx += 256)
        Qt[(150 + idx/64)*70 + (idx & 63)] = 0.f;
    if (tid < 64) { rowm[tid] = -INFINITY; rowl[tid] = 0.f; }

    u64t O2[4][10];
    #pragma unroll
    for (int i = 0; i < 4; i++)
        #pragma unroll
        for (int j = 0; j < 10; j++) O2[i][j] = 0ull;
    __syncthreads();

    for (int qt = 0; qt < 32; qt++) {
        const int q0 = qt * 64;
        // stage P tile [q][h] stride 154
        for (int idx = tid; idx < 64*75; idx += 256) {
            int r = idx / 75, c = idx - r*75;
            *(float2*)&Ps[r*154 + 2*c] =
                *(const float2*)&g_P[base + (size_t)(q0 + r)*Hk + 2*c];
        }
        // stage Qh transposed tile [h][q] stride 70
        {
            size_t t64 = (size_t)(b*32 + qt) * Hk;
            for (int idx = tid; idx < 150*32; idx += 256) {
                int h = idx >> 5, c = idx & 31;
                *(float2*)&Qt[h*70 + 2*c] =
                    *(const float2*)&g_Qt[(t64 + h)*64 + 2*c];
            }
        }
        __syncthreads();

        // S[a][q] = <Ah[a], P[q]>, f32x2 packed along k (even/odd lanes)
        {
            u64t s2[4][4];
            #pragma unroll
            for (int i = 0; i < 4; i++)
                #pragma unroll
                for (int j = 0; j < 4; j++) s2[i][j] = 0ull;
            #pragma unroll 3
            for (int k = 0; k < Hk; k += 2) {
                u64t av[4], pv[4];
                #pragma unroll
                for (int i = 0; i < 4; i++)
                    av[i] = *(const u64t*)&Ahs[(ty4 + i)*154 + k];
                #pragma unroll
                for (int j = 0; j < 4; j++)
                    pv[j] = *(const u64t*)&Ps[(tx + 16*j)*154 + k];
                #pragma unroll
                for (int i = 0; i < 4; i++)
                    #pragma unroll
                    for (int j = 0; j < 4; j++)
                        ffma2(s2[i][j], av[i], pv[j]);
            }
            #pragma unroll
            for (int i = 0; i < 4; i++)
                #pragma unroll
                for (int j = 0; j < 4; j++)
                    Ss[(ty4 + i)*66 + tx + 16*j] = lo_f(s2[i][j]) + hi_f(s2[i][j]);
        }
        __syncthreads();

        // online softmax over q (4 threads per a-row)
        {
            int row = tid >> 2, t4 = tid & 3;
            float mx = -INFINITY;
            #pragma unroll
            for (int q = 0; q < 16; q++) mx = fmaxf(mx, Ss[row*66 + t4*16 + q]);
            mx = fmaxf(mx, __shfl_xor_sync(0xffffffffu, mx, 1));
            mx = fmaxf(mx, __shfl_xor_sync(0xffffffffu, mx, 2));
            float mold = rowm[row];
            float mnew = fmaxf(mold, mx);
            float ssum = 0.f;
            #pragma unroll
            for (int q = 0; q < 16; q++) {
                float e = __expf(Ss[row*66 + t4*16 + q] - mnew);
                Ss[row*66 + t4*16 + q] = e;
                ssum += e;
            }
            ssum += __shfl_xor_sync(0xffffffffu, ssum, 1);
            ssum += __shfl_xor_sync(0xffffffffu, ssum, 2);
            if (t4 == 0) {
                float al = __expf(mold - mnew);
                alph[row] = al;
                rowl[row] = rowl[row] * al + ssum;
                rowm[row] = mnew;
            }
        }
        __syncthreads();

        // rescale O2, accumulate O += E @ Qh^T (f32x2 packed along q)
        {
            #pragma unroll
            for (int i = 0; i < 4; i++) {
                float al = alph[ty4 + i];
                u64t a2 = pack2(al, al);
                #pragma unroll
                for (int j = 0; j < 10; j++) O2[i][j] = fmul2(O2[i][j], a2);
            }
            #pragma unroll 2
            for (int q = 0; q < 64; q += 2) {
                u64t ev[4], qv[10];
                #pragma unroll
                for (int i = 0; i < 4; i++)
                    ev[i] = *(const u64t*)&Ss[(ty4 + i)*66 + q];
                #pragma unroll
                for (int j = 0; j < 10; j++)
                    qv[j] = *(const u64t*)&Qt[(tx + 16*j)*70 + q];
                #pragma unroll
                for (int i = 0; i < 4; i++)
                    #pragma unroll
                    for (int j = 0; j < 10; j++)
                        ffma2(O2[i][j], ev[i], qv[j]);
            }
        }
        __syncthreads();
    }

    // normalize, stage Hm into Ps buffer (stride 154)
    {
        float linv[4];
        #pragma unroll
        for (int i = 0; i < 4; i++) linv[i] = 1.f / rowl[ty4 + i];
        #pragma unroll
        for (int i = 0; i < 4; i++)
            #pragma unroll
            for (int j = 0; j < 10; j++) {
                int n = tx + 16*j;
                if (n < Hk)
                    Ps[(ty4 + i)*154 + n] = (lo_f(O2[i][j]) + hi_f(O2[i][j])) * linv[i];
            }
    }
    __syncthreads();

    // epilogue: T = relu([Ah, Hm] @ Wt + bt)
    float acc[4][10];
    #pragma unroll
    for (int j = 0; j < 10; j++) {
        int n = tx + 16*j;
        float bb = (n < Hk) ? bt[n] : 0.f;
        #pragma unroll
        for (int i = 0; i < 4; i++) acc[i][j] = bb;
    }
    for (int h = 0; h < Hk; h++) {
        float av[4], ov[4];
        #pragma unroll
        for (int i = 0; i < 4; i++) {
            av[i] = Ahs[(ty4 + i)*154 + h];
            ov[i] = Ps [(ty4 + i)*154 + h];
        }
        #pragma unroll
        for (int j = 0; j < 10; j++) {
            int n = tx + 16*j;
            float w1 = (n < Hk) ? __ldg(&Wt[h*Hk + n])        : 0.f;
            float w2 = (n < Hk) ? __ldg(&Wt[(Hk + h)*Hk + n]) : 0.f;
            #pragma unroll
            for (int i = 0; i < 4; i++) acc[i][j] += av[i]*w1 + ov[i]*w2;
        }
    }
    #pragma unroll
    for (int i = 0; i < 4; i++)
        #pragma unroll
        for (int j = 0; j < 10; j++) {
            int n = tx + 16*j;
            if (n < Hk)
                out[base + (size_t)(a0 + ty4 + i)*Hk + n] = fmaxf(acc[i][j], 0.f);
        }
}

// ---------------------------------------------------------------------------
extern "C" void kernel_launch(void* const* d_in, const int* in_sizes, int n_in,
                              void* d_out, int out_size)
{
    const float* Q  = (const float*)d_in[0];
    const float* A  = (const float*)d_in[1];
    const float* Wi = (const float*)d_in[2];
    const float* Wu = (const float*)d_in[3];
    const float* Wg = (const float*)d_in[4];
    const float* Wt = (const float*)d_in[5];
    const float* bi = (const float*)d_in[6];
    const float* bu = (const float*)d_in[7];
    const float* bg = (const float*)d_in[8];
    const float* bt = (const float*)d_in[9];
    float* out = (float*)d_out;

    cudaFuncSetAttribute(attn_kernel,
                         cudaFuncAttributeMaxDynamicSharedMemorySize,
                         SMEM_ATTN_FLOATS * sizeof(float));

    gate_kernel<<<1024, 256>>>(Q, A, Wi, Wu, Wg, bi, bu, bg);
    attn_kernel<<<dim3(Lseq/64, Bq), 256, SMEM_ATTN_FLOATS * sizeof(float)>>>(Wt, bt, out);
}

// round 9
// speedup vs baseline: 1.9934x; 1.6796x over previous
#include <cuda_runtime.h>
#include <math.h>
#include <stdint.h>

#define Bq   8
#define Lseq 2048
#define Dk   300
#define Hk   150
#define NROWS (Bq*Lseq)     // 16384

// scratch (allocation-free rule -> __device__ globals), padded to 160 cols (zeros)
__device__ float g_Ah[(size_t)NROWS*160];
__device__ float g_P [(size_t)NROWS*160];
__device__ float g_Qh[(size_t)NROWS*160];

// ---------------- f32x2 helpers ----------------
typedef unsigned long long u64t;
__device__ __forceinline__ void ffma2(u64t &d, u64t a, u64t b) {
    asm("fma.rn.f32x2 %0, %1, %2, %0;" : "+l"(d) : "l"(a), "l"(b));
}
__device__ __forceinline__ float lo_f(u64t v){ return __uint_as_float((unsigned)v); }
__device__ __forceinline__ float hi_f(u64t v){ return __uint_as_float((unsigned)(v>>32)); }
__device__ __forceinline__ u64t pack2(float x, float y){
    u64t d; asm("mov.b64 %0, {%1,%2};" : "=l"(d)
                : "r"(__float_as_uint(x)), "r"(__float_as_uint(y))); return d;
}

// ---------------- tf32 mma helpers (plain mma.sync, no 'a' features) ----------------
__device__ __forceinline__ void mma8(float* c, uint32_t a0, uint32_t a1,
                                     uint32_t a2, uint32_t a3,
                                     uint32_t b0, uint32_t b1) {
    asm volatile(
        "mma.sync.aligned.m16n8k8.row.col.f32.tf32.tf32.f32 "
        "{%0,%1,%2,%3}, {%4,%5,%6,%7}, {%8,%9}, {%0,%1,%2,%3};"
        : "+f"(c[0]), "+f"(c[1]), "+f"(c[2]), "+f"(c[3])
        : "r"(a0), "r"(a1), "r"(a2), "r"(a3), "r"(b0), "r"(b1));
}
// split x into tf32 hi (truncate) + residual lo
__device__ __forceinline__ void split32(float x, uint32_t &hi, uint32_t &lo) {
    uint32_t xb = __float_as_uint(x);
    hi = xb & 0xFFFFE000u;
    lo = __float_as_uint(x - __uint_as_float(hi));
}

// fast exp via FMA-pipe polynomial (avoids MUFU bottleneck); x <= 0 expected
__device__ __forceinline__ float fexp(float x) {
    float y = fmaxf(x * 1.4426950408889634f, -126.0f);
    int   ii = __float2int_rn(y);
    float f = y - (float)ii;
    float p = 0.0013333558f;
    p = p*f + 0.009618129f;
    p = p*f + 0.055504109f;
    p = p*f + 0.24022651f;
    p = p*f + 0.69314718f;
    p = p*f + 1.0f;
    return __int_as_float((ii + 127) << 23) * p;
}

// ---------------------------------------------------------------------------
// Kernel 1: gated projection (f32x2 over n-pairs); Q blocks fuse P = Qh@Wg+bg
// ---------------------------------------------------------------------------
__global__ __launch_bounds__(256) void gate_kernel(
    const float* __restrict__ Q, const float* __restrict__ A,
    const float* __restrict__ Wi, const float* __restrict__ Wu,
    const float* __restrict__ Wg,
    const float* __restrict__ bi, const float* __restrict__ bu,
    const float* __restrict__ bg)
{
    __shared__ float sm[10560];
    float* Xs  = sm;          // [32][30]
    float* Wis = sm + 960;    // [30][160]
    float* Wus = sm + 5760;   // [30][160]
    float* Qhs = sm;          // [32][160] (P phase)
    float* Wgs = sm + 5760;   // [30][160] (P phase)

    const int tid = threadIdx.x;
    const int tx = tid & 15, ty = tid >> 4;
    const bool isQ = (blockIdx.x < 512);
    const int row0 = (blockIdx.x & 511) * 32;
    const float* X = isQ ? Q : A;

    u64t ai2[2][5], au2[2][5];
    #pragma unroll
    for (int i = 0; i < 2; i++)
        #pragma unroll
        for (int jp = 0; jp < 5; jp++) { ai2[i][jp] = 0ull; au2[i][jp] = 0ull; }

    for (int kt = 0; kt < 10; kt++) {
        for (int idx = tid; idx < 32*30; idx += 256) {
            int m = idx / 30, kk = idx - m*30;
            Xs[idx] = X[(size_t)(row0 + m) * Dk + kt*30 + kk];
        }
        for (int idx = tid; idx < 30*160; idx += 256) {
            int kk = idx / 160, n = idx - kk*160;
            float wi = 0.f, wu = 0.f;
            if (n < Hk) { int g = (kt*30 + kk) * Hk + n; wi = Wi[g]; wu = Wu[g]; }
            Wis[idx] = wi; Wus[idx] = wu;
        }
        __syncthreads();
        #pragma unroll 5
        for (int k = 0; k < 30; k++) {
            float x0 = Xs[(ty*2    )*30 + k];
            float x1 = Xs[(ty*2 + 1)*30 + k];
            u64t x0p = pack2(x0, x0), x1p = pack2(x1, x1);
            #pragma unroll
            for (int jp = 0; jp < 5; jp++) {
                u64t wi = *(const u64t*)&Wis[k*160 + 2*(tx + 16*jp)];
                u64t wu = *(const u64t*)&Wus[k*160 + 2*(tx + 16*jp)];
                ffma2(ai2[0][jp], x0p, wi); ffma2(ai2[1][jp], x1p, wi);
                ffma2(au2[0][jp], x0p, wu); ffma2(au2[1][jp], x1p, wu);
            }
        }
        __syncthreads();
    }

    // nonlinearity
    float hv[2][10];
    #pragma unroll
    for (int i = 0; i < 2; i++)
        #pragma unroll
        for (int jp = 0; jp < 5; jp++) {
            int n0 = 2*(tx + 16*jp);
            bool v = (n0 < Hk);
            float bi0 = v ? bi[n0] : 0.f, bi1 = v ? bi[n0+1] : 0.f;
            float bu0 = v ? bu[n0] : 0.f, bu1 = v ? bu[n0+1] : 0.f;
            float s0 = 1.f/(1.f + __expf(-(lo_f(ai2[i][jp]) + bi0)));
            float s1 = 1.f/(1.f + __expf(-(hi_f(ai2[i][jp]) + bi1)));
            float h0 = s0 * tanhf(lo_f(au2[i][jp]) + bu0);
            float h1 = s1 * tanhf(hi_f(au2[i][jp]) + bu1);
            hv[i][jp*2]   = v ? h0 : 0.f;
            hv[i][jp*2+1] = v ? h1 : 0.f;
        }

    float* dst = isQ ? g_Qh : g_Ah;
    #pragma unroll
    for (int i = 0; i < 2; i++)
        #pragma unroll
        for (int jp = 0; jp < 5; jp++) {
            int n0 = 2*(tx + 16*jp);
            *(u64t*)&dst[(size_t)(row0 + ty*2 + i)*160 + n0] =
                pack2(hv[i][jp*2], hv[i][jp*2+1]);
        }
    if (!isQ) return;

    // P = Qh @ Wg + bg
    __syncthreads();
    #pragma unroll
    for (int i = 0; i < 2; i++)
        #pragma unroll
        for (int jp = 0; jp < 5; jp++) {
            int n0 = 2*(tx + 16*jp);
            *(u64t*)&Qhs[(ty*2 + i)*160 + n0] = pack2(hv[i][jp*2], hv[i][jp*2+1]);
        }
    __syncthreads();

    u64t ap2[2][5];
    #pragma unroll
    for (int i = 0; i < 2; i++)
        #pragma unroll
        for (int jp = 0; jp < 5; jp++) ap2[i][jp] = 0ull;

    for (int kt = 0; kt < 5; kt++) {
        for (int idx = tid; idx < 30*160; idx += 256) {
            int kk = idx / 160, n = idx - kk*160;
            Wgs[idx] = (n < Hk) ? Wg[(kt*30 + kk) * Hk + n] : 0.f;
        }
        __syncthreads();
        #pragma unroll 5
        for (int k = 0; k < 30; k++) {
            float q0 = Qhs[(ty*2    )*160 + kt*30 + k];
            float q1 = Qhs[(ty*2 + 1)*160 + kt*30 + k];
            u64t q0p = pack2(q0, q0), q1p = pack2(q1, q1);
            #pragma unroll
            for (int jp = 0; jp < 5; jp++) {
                u64t wg = *(const u64t*)&Wgs[k*160 + 2*(tx + 16*jp)];
                ffma2(ap2[0][jp], q0p, wg);
                ffma2(ap2[1][jp], q1p, wg);
            }
        }
        __syncthreads();
    }
    #pragma unroll
    for (int i = 0; i < 2; i++)
        #pragma unroll
        for (int jp = 0; jp < 5; jp++) {
            int n0 = 2*(tx + 16*jp);
            bool v = (n0 < Hk);
            float p0 = v ? lo_f(ap2[i][jp]) + bg[n0]   : 0.f;
            float p1 = v ? hi_f(ap2[i][jp]) + bg[n0+1] : 0.f;
            *(u64t*)&g_P[(size_t)(row0 + ty*2 + i)*160 + n0] = pack2(p0, p1);
        }
}

// ---------------------------------------------------------------------------
// Kernel 2: one-pass flash attention on mma.sync tf32 (3x-split), fused epilogue
// grid (16, 8); 256 threads = 8 warps x 16 a-rows. 1 CTA/SM.
// smem floats: Ahs[128][164] | Ps[64][164] | Qs[64][168] | Es[128][68]
//   (Ps+Qs reused as hm[128][154] after the main loop)
// ---------------------------------------------------------------------------
#define ST_A 164
#define ST_P 164
#define ST_Q 168
#define ST_E 68
#define ST_H 154
#define OFF_P   (128*ST_A)                    // 20992 floats
#define OFF_Q   (OFF_P + 64*ST_P)             // 31488
#define OFF_E   (OFF_Q + 64*ST_Q)             // 42240
#define SMF_TOT (OFF_E + 128*ST_E)            // 50944 floats = 203776 B

__global__ __launch_bounds__(256, 1) void attn_kernel(
    const float* __restrict__ Wt, const float* __restrict__ bt,
    float* __restrict__ out)
{
    extern __shared__ __align__(16) float sm[];
    float* Ahs = sm;
    float* Ps  = sm + OFF_P;
    float* Qs  = sm + OFF_Q;
    float* Es  = sm + OFF_E;
    float* hm  = sm + OFF_P;   // overlay after main loop

    const int tid = threadIdx.x;
    const int wid = tid >> 5, lane = tid & 31;
    const int g = lane >> 2, tig = lane & 3;
    const int rb = wid * 16;
    const int b = blockIdx.y, a0 = blockIdx.x * 128;
    const size_t base = (size_t)b * Lseq * 160;

    // stage Ah [128][160] -> stride 164
    #pragma unroll 4
    for (int t = 0; t < 20; t++) {
        int idx = tid + t*256;
        int r = idx / 40, c4 = idx - r*40;
        *(float4*)&Ahs[r*ST_A + c4*4] =
            *(const float4*)&g_Ah[base + (size_t)(a0 + r)*160 + c4*4];
    }

    float o[19][4];
    #pragma unroll
    for (int j = 0; j < 19; j++)
        #pragma unroll
        for (int e = 0; e < 4; e++) o[j][e] = 0.f;
    float m0 = -INFINITY, m1 = -INFINITY, l0 = 0.f, l1 = 0.f;

    for (int qt = 0; qt < 32; qt++) {
        const size_t qb = base + (size_t)qt * 64 * 160;
        #pragma unroll 2
        for (int t = 0; t < 10; t++) {
            int idx = tid + t*256;
            int q = idx / 40, c4 = idx - q*40;
            *(float4*)&Ps[q*ST_P + c4*4] = *(const float4*)&g_P [qb + (size_t)q*160 + c4*4];
            *(float4*)&Qs[q*ST_Q + c4*4] = *(const float4*)&g_Qh[qb + (size_t)q*160 + c4*4];
        }
        __syncthreads();

        // ---- S = Ah @ P^T : 16 rows x 64 q per warp, k = 152, 3x tf32 ----
        float s[8][4];
        #pragma unroll
        for (int j = 0; j < 8; j++)
            #pragma unroll
            for (int e = 0; e < 4; e++) s[j][e] = 0.f;
        #pragma unroll 1
        for (int t = 0; t < 19; t++) {
            int k0 = t*8;
            uint32_t ah[4], al[4];
            split32(Ahs[(rb+g  )*ST_A + k0+tig  ], ah[0], al[0]);
            split32(Ahs[(rb+g+8)*ST_A + k0+tig  ], ah[1], al[1]);
            split32(Ahs[(rb+g  )*ST_A + k0+tig+4], ah[2], al[2]);
            split32(Ahs[(rb+g+8)*ST_A + k0+tig+4], ah[3], al[3]);
            #pragma unroll
            for (int j = 0; j < 8; j++) {
                uint32_t bh0, bl0, bh1, bl1;
                split32(Ps[(8*j+g)*ST_P + k0+tig  ], bh0, bl0);
                split32(Ps[(8*j+g)*ST_P + k0+tig+4], bh1, bl1);
                mma8(s[j], ah[0], ah[1], ah[2], ah[3], bh0, bh1);
                mma8(s[j], ah[0], ah[1], ah[2], ah[3], bl0, bl1);
                mma8(s[j], al[0], al[1], al[2], al[3], bh0, bh1);
            }
        }

        // ---- online softmax (warp-local rows) ----
        float mx0 = -INFINITY, mx1 = -INFINITY;
        #pragma unroll
        for (int j = 0; j < 8; j++) {
            mx0 = fmaxf(mx0, fmaxf(s[j][0], s[j][1]));
            mx1 = fmaxf(mx1, fmaxf(s[j][2], s[j][3]));
        }
        mx0 = fmaxf(mx0, __shfl_xor_sync(0xffffffffu, mx0, 1));
        mx0 = fmaxf(mx0, __shfl_xor_sync(0xffffffffu, mx0, 2));
        mx1 = fmaxf(mx1, __shfl_xor_sync(0xffffffffu, mx1, 1));
        mx1 = fmaxf(mx1, __shfl_xor_sync(0xffffffffu, mx1, 2));
        float mn0 = fmaxf(m0, mx0), mn1 = fmaxf(m1, mx1);
        float al0 = fexp(m0 - mn0), al1 = fexp(m1 - mn1);
        #pragma unroll
        for (int j = 0; j < 19; j++) {
            o[j][0] *= al0; o[j][1] *= al0;
            o[j][2] *= al1; o[j][3] *= al1;
        }
        float sum0 = 0.f, sum1 = 0.f;
        #pragma unroll
        for (int j = 0; j < 8; j++) {
            float e0 = fexp(s[j][0] - mn0);
            float e1 = fexp(s[j][1] - mn0);
            float e2 = fexp(s[j][2] - mn1);
            float e3 = fexp(s[j][3] - mn1);
            sum0 += e0 + e1; sum1 += e2 + e3;
            *(float2*)&Es[(rb+g  )*ST_E + 8*j + 2*tig] = make_float2(e0, e1);
            *(float2*)&Es[(rb+g+8)*ST_E + 8*j + 2*tig] = make_float2(e2, e3);
        }
        sum0 += __shfl_xor_sync(0xffffffffu, sum0, 1);
        sum0 += __shfl_xor_sync(0xffffffffu, sum0, 2);
        sum1 += __shfl_xor_sync(0xffffffffu, sum1, 1);
        sum1 += __shfl_xor_sync(0xffffffffu, sum1, 2);
        l0 = l0*al0 + sum0; m0 = mn0;
        l1 = l1*al1 + sum1; m1 = mn1;
        __syncwarp();

        // ---- O += E @ Qh : 16 rows x 152 h per warp, k = 64, 3x tf32 ----
        #pragma unroll 1
        for (int t = 0; t < 8; t++) {
            int k0 = t*8;
            uint32_t eh[4], el[4];
            split32(Es[(rb+g  )*ST_E + k0+tig  ], eh[0], el[0]);
            split32(Es[(rb+g+8)*ST_E + k0+tig  ], eh[1], el[1]);
            split32(Es[(rb+g  )*ST_E + k0+tig+4], eh[2], el[2]);
            split32(Es[(rb+g+8)*ST_E + k0+tig+4], eh[3], el[3]);
            #pragma unroll
            for (int j = 0; j < 19; j++) {
                uint32_t bh0, bl0, bh1, bl1;
                split32(Qs[(k0+tig  )*ST_Q + 8*j + g], bh0, bl0);
                split32(Qs[(k0+tig+4)*ST_Q + 8*j + g], bh1, bl1);
                mma8(o[j], eh[0], eh[1], eh[2], eh[3], bh0, bh1);
                mma8(o[j], eh[0], eh[1], eh[2], eh[3], bl0, bl1);
                mma8(o[j], el[0], el[1], el[2], el[3], bh0, bh1);
            }
        }
        __syncthreads();   // Ps/Qs free for next tile
    }

    // ---- normalize O into hm (overlay Ps/Qs) ----
    {
        float inv0 = 1.f / l0, inv1 = 1.f / l1;
        #pragma unroll
        for (int j = 0; j < 19; j++) {
            int c = 8*j + 2*tig;
            if (c < Hk) {
                *(float2*)&hm[(rb+g  )*ST_H + c] =
                    make_float2(o[j][0]*inv0, o[j][1]*inv0);
                *(float2*)&hm[(rb+g+8)*ST_H + c] =
                    make_float2(o[j][2]*inv1, o[j][3]*inv1);
            }
        }
    }
    __syncthreads();

    // ---- epilogue: T = relu([Ah, Hm] @ Wt + bt), f32x2 SIMT ----
    {
        const int tx = tid & 15, tyy = tid >> 4;
        u64t acc2[8][5];
        #pragma unroll
        for (int jp = 0; jp < 5; jp++) {
            int p = tx + 16*jp;
            u64t bb = (p < 75) ? *(const u64t*)&bt[2*p] : 0ull;
            #pragma unroll
            for (int i = 0; i < 8; i++) acc2[i][jp] = bb;
        }
        for (int h = 0; h < Hk; h++) {
            u64t avp[8];
            #pragma unroll
            for (int i = 0; i < 8; i++) {
                float a = Ahs[(tyy + 16*i)*ST_A + h];
                avp[i] = pack2(a, a);
            }
            #pragma unroll
            for (int jp = 0; jp < 5; jp++) {
                int p = tx + 16*jp;
                u64t w = (p < 75) ? *(const u64t*)&Wt[(size_t)h*Hk + 2*p] : 0ull;
                #pragma unroll
                for (int i = 0; i < 8; i++) ffma2(acc2[i][jp], avp[i], w);
            }
        }
        for (int h = 0; h < Hk; h++) {
            u64t ovp[8];
            #pragma unroll
            for (int i = 0; i < 8; i++) {
                float ov = hm[(tyy + 16*i)*ST_H + h];
                ovp[i] = pack2(ov, ov);
            }
            #pragma unroll
            for (int jp = 0; jp < 5; jp++) {
                int p = tx + 16*jp;
                u64t w = (p < 75) ? *(const u64t*)&Wt[(size_t)(Hk + h)*Hk + 2*p] : 0ull;
                #pragma unroll
                for (int i = 0; i < 8; i++) ffma2(acc2[i][jp], ovp[i], w);
            }
        }
        #pragma unroll
        for (int i = 0; i < 8; i++)
            #pragma unroll
            for (int jp = 0; jp < 5; jp++) {
                int p = tx + 16*jp;
                if (p < 75) {
                    int r = tyy + 16*i;
                    float v0 = fmaxf(lo_f(acc2[i][jp]), 0.f);
                    float v1 = fmaxf(hi_f(acc2[i][jp]), 0.f);
                    *(u64t*)&out[((size_t)b*Lseq + a0 + r)*Hk + 2*p] = pack2(v0, v1);
                }
            }
    }
}

// ---------------------------------------------------------------------------
extern "C" void kernel_launch(void* const* d_in, const int* in_sizes, int n_in,
                              void* d_out, int out_size)
{
    const float* Q  = (const float*)d_in[0];
    const float* A  = (const float*)d_in[1];
    const float* Wi = (const float*)d_in[2];
    const float* Wu = (const float*)d_in[3];
    const float* Wg = (const float*)d_in[4];
    const float* Wt = (const float*)d_in[5];
    const float* bi = (const float*)d_in[6];
    const float* bu = (const float*)d_in[7];
    const float* bg = (const float*)d_in[8];
    const float* bt = (const float*)d_in[9];
    float* out = (float*)d_out;

    cudaFuncSetAttribute(attn_kernel,
                         cudaFuncAttributeMaxDynamicSharedMemorySize,
                         SMF_TOT * (int)sizeof(float));

    gate_kernel<<<1024, 256>>>(Q, A, Wi, Wu, Wg, bi, bu, bg);
    attn_kernel<<<dim3(16, Bq), 256, SMF_TOT * sizeof(float)>>>(Wt, bt, out);
}

// round 12
// speedup vs baseline: 2.0540x; 1.0304x over previous
#include <cuda_runtime.h>
#include <math.h>
#include <stdint.h>

#define Bq   8
#define Lseq 2048
#define Dk   300
#define Hk   150
#define NROWS (Bq*Lseq)     // 16384

// scratch (allocation-free rule -> __device__ globals), padded to 160 cols (zeros)
__device__ float g_Ah[(size_t)NROWS*160];
__device__ float g_P [(size_t)NROWS*160];
__device__ float g_Qh[(size_t)NROWS*160];

// ---------------- f32x2 helpers ----------------
typedef unsigned long long u64t;
__device__ __forceinline__ void ffma2(u64t &d, u64t a, u64t b) {
    asm("fma.rn.f32x2 %0, %1, %2, %0;" : "+l"(d) : "l"(a), "l"(b));
}
__device__ __forceinline__ float lo_f(u64t v){ return __uint_as_float((unsigned)v); }
__device__ __forceinline__ float hi_f(u64t v){ return __uint_as_float((unsigned)(v>>32)); }
__device__ __forceinline__ u64t pack2(float x, float y){
    u64t d; asm("mov.b64 %0, {%1,%2};" : "=l"(d)
                : "r"(__float_as_uint(x)), "r"(__float_as_uint(y))); return d;
}

// ---------------- tf32 mma helpers (plain mma.sync, no 'a' features) ----------------
__device__ __forceinline__ void mma8(float* c, uint32_t a0, uint32_t a1,
                                     uint32_t a2, uint32_t a3,
                                     uint32_t b0, uint32_t b1) {
    asm volatile(
        "mma.sync.aligned.m16n8k8.row.col.f32.tf32.tf32.f32 "
        "{%0,%1,%2,%3}, {%4,%5,%6,%7}, {%8,%9}, {%0,%1,%2,%3};"
        : "+f"(c[0]), "+f"(c[1]), "+f"(c[2]), "+f"(c[3])
        : "r"(a0), "r"(a1), "r"(a2), "r"(a3), "r"(b0), "r"(b1));
}
// split x into tf32 hi (truncate) + residual lo
__device__ __forceinline__ void split32(float x, uint32_t &hi, uint32_t &lo) {
    uint32_t xb = __float_as_uint(x);
    hi = xb & 0xFFFFE000u;
    lo = __float_as_uint(x - __uint_as_float(hi));
}

// fast exp via FMA-pipe polynomial (avoids MUFU bottleneck); x <= 0 expected
__device__ __forceinline__ float fexp(float x) {
    float y = fmaxf(x * 1.4426950408889634f, -126.0f);
    int   ii = __float2int_rn(y);
    float f = y - (float)ii;
    float p = 0.0013333558f;
    p = p*f + 0.009618129f;
    p = p*f + 0.055504109f;
    p = p*f + 0.24022651f;
    p = p*f + 0.69314718f;
    p = p*f + 1.0f;
    return __int_as_float((ii + 127) << 23) * p;
}

// ---------------------------------------------------------------------------
// Kernel 1: gated projection (f32x2 over n-pairs); Q blocks fuse P = Qh@Wg+bg
// ---------------------------------------------------------------------------
__global__ __launch_bounds__(256) void gate_kernel(
    const float* __restrict__ Q, const float* __restrict__ A,
    const float* __restrict__ Wi, const float* __restrict__ Wu,
    const float* __restrict__ Wg,
    const float* __restrict__ bi, const float* __restrict__ bu,
    const float* __restrict__ bg)
{
    __shared__ float sm[10560];
    float* Xs  = sm;          // [32][30]
    float* Wis = sm + 960;    // [30][160]
    float* Wus = sm + 5760;   // [30][160]
    float* Qhs = sm;          // [32][160] (P phase)
    float* Wgs = sm + 5760;   // [30][160] (P phase)

    const int tid = threadIdx.x;
    const int tx = tid & 15, ty = tid >> 4;
    const bool isQ = (blockIdx.x < 512);
    const int row0 = (blockIdx.x & 511) * 32;
    const float* X = isQ ? Q : A;

    u64t ai2[2][5], au2[2][5];
    #pragma unroll
    for (int i = 0; i < 2; i++)
        #pragma unroll
        for (int jp = 0; jp < 5; jp++) { ai2[i][jp] = 0ull; au2[i][jp] = 0ull; }

    for (int kt = 0; kt < 10; kt++) {
        for (int idx = tid; idx < 32*30; idx += 256) {
            int m = idx / 30, kk = idx - m*30;
            Xs[idx] = X[(size_t)(row0 + m) * Dk + kt*30 + kk];
        }
        for (int idx = tid; idx < 30*160; idx += 256) {
            int kk = idx / 160, n = idx - kk*160;
            float wi = 0.f, wu = 0.f;
            if (n < Hk) { int g = (kt*30 + kk) * Hk + n; wi = Wi[g]; wu = Wu[g]; }
            Wis[idx] = wi; Wus[idx] = wu;
        }
        __syncthreads();
        #pragma unroll 5
        for (int k = 0; k < 30; k++) {
            float x0 = Xs[(ty*2    )*30 + k];
            float x1 = Xs[(ty*2 + 1)*30 + k];
            u64t x0p = pack2(x0, x0), x1p = pack2(x1, x1);
            #pragma unroll
            for (int jp = 0; jp < 5; jp++) {
                u64t wi = *(const u64t*)&Wis[k*160 + 2*(tx + 16*jp)];
                u64t wu = *(const u64t*)&Wus[k*160 + 2*(tx + 16*jp)];
                ffma2(ai2[0][jp], x0p, wi); ffma2(ai2[1][jp], x1p, wi);
                ffma2(au2[0][jp], x0p, wu); ffma2(au2[1][jp], x1p, wu);
            }
        }
        __syncthreads();
    }

    // nonlinearity
    float hv[2][10];
    #pragma unroll
    for (int i = 0; i < 2; i++)
        #pragma unroll
        for (int jp = 0; jp < 5; jp++) {
            int n0 = 2*(tx + 16*jp);
            bool v = (n0 < Hk);
            float bi0 = v ? bi[n0] : 0.f, bi1 = v ? bi[n0+1] : 0.f;
            float bu0 = v ? bu[n0] : 0.f, bu1 = v ? bu[n0+1] : 0.f;
            float s0 = 1.f/(1.f + __expf(-(lo_f(ai2[i][jp]) + bi0)));
            float s1 = 1.f/(1.f + __expf(-(hi_f(ai2[i][jp]) + bi1)));
            float h0 = s0 * tanhf(lo_f(au2[i][jp]) + bu0);
            float h1 = s1 * tanhf(hi_f(au2[i][jp]) + bu1);
            hv[i][jp*2]   = v ? h0 : 0.f;
            hv[i][jp*2+1] = v ? h1 : 0.f;
        }

    float* dst = isQ ? g_Qh : g_Ah;
    #pragma unroll
    for (int i = 0; i < 2; i++)
        #pragma unroll
        for (int jp = 0; jp < 5; jp++) {
            int n0 = 2*(tx + 16*jp);
            *(u64t*)&dst[(size_t)(row0 + ty*2 + i)*160 + n0] =
                pack2(hv[i][jp*2], hv[i][jp*2+1]);
        }
    if (!isQ) return;

    // P = Qh @ Wg + bg
    __syncthreads();
    #pragma unroll
    for (int i = 0; i < 2; i++)
        #pragma unroll
        for (int jp = 0; jp < 5; jp++) {
            int n0 = 2*(tx + 16*jp);
            *(u64t*)&Qhs[(ty*2 + i)*160 + n0] = pack2(hv[i][jp*2], hv[i][jp*2+1]);
        }
    __syncthreads();

    u64t ap2[2][5];
    #pragma unroll
    for (int i = 0; i < 2; i++)
        #pragma unroll
        for (int jp = 0; jp < 5; jp++) ap2[i][jp] = 0ull;

    for (int kt = 0; kt < 5; kt++) {
        for (int idx = tid; idx < 30*160; idx += 256) {
            int kk = idx / 160, n = idx - kk*160;
            Wgs[idx] = (n < Hk) ? Wg[(kt*30 + kk) * Hk + n] : 0.f;
        }
        __syncthreads();
        #pragma unroll 5
        for (int k = 0; k < 30; k++) {
            float q0 = Qhs[(ty*2    )*160 + kt*30 + k];
            float q1 = Qhs[(ty*2 + 1)*160 + kt*30 + k];
            u64t q0p = pack2(q0, q0), q1p = pack2(q1, q1);
            #pragma unroll
            for (int jp = 0; jp < 5; jp++) {
                u64t wg = *(const u64t*)&Wgs[k*160 + 2*(tx + 16*jp)];
                ffma2(ap2[0][jp], q0p, wg);
                ffma2(ap2[1][jp], q1p, wg);
            }
        }
        __syncthreads();
    }
    #pragma unroll
    for (int i = 0; i < 2; i++)
        #pragma unroll
        for (int jp = 0; jp < 5; jp++) {
            int n0 = 2*(tx + 16*jp);
            bool v = (n0 < Hk);
            float p0 = v ? lo_f(ap2[i][jp]) + bg[n0]   : 0.f;
            float p1 = v ? hi_f(ap2[i][jp]) + bg[n0+1] : 0.f;
            *(u64t*)&g_P[(size_t)(row0 + ty*2 + i)*160 + n0] = pack2(p0, p1);
        }
}

// ---------------------------------------------------------------------------
// Kernel 2: one-pass flash attention, mma.sync tf32 3x-split, 512 threads.
// Warp pair (w, w+8) shares 16 a-rows: S split along q (32 each),
// O split along h (j 0..9 / 9..18, overlap j=9 writes identical values).
// Cross-warp softmax merge via pmax/psum smem.
// ---------------------------------------------------------------------------
#define ST_A 164
#define ST_P 164
#define ST_Q 168
#define ST_E 68
#define ST_H 154
#define OFF_P   (128*ST_A)                    // 20992 floats
#define OFF_Q   (OFF_P + 64*ST_P)             // 31488
#define OFF_E   (OFF_Q + 64*ST_Q)             // 42240
#define OFF_PM  (OFF_E + 128*ST_E)            // 50944
#define OFF_PS  (OFF_PM + 256)                // 51200
#define SMF_TOT (OFF_PS + 256)                // 51456 floats = 205824 B

__global__ __launch_bounds__(512, 1) void attn_kernel(
    const float* __restrict__ Wt, const float* __restrict__ bt,
    float* __restrict__ out)
{
    extern __shared__ __align__(16) float sm[];
    float* Ahs  = sm;
    float* Ps   = sm + OFF_P;
    float* Qs   = sm + OFF_Q;
    float* Es   = sm + OFF_E;
    float* pmax = sm + OFF_PM;   // [2][128]
    float* psum = sm + OFF_PS;   // [2][128]
    float* hm   = sm + OFF_P;    // overlay after main loop

    const int tid = threadIdx.x;
    const int wid = tid >> 5, lane = tid & 31;
    const int g = lane >> 2, tig = lane & 3;
    const int half = wid >> 3;              // 0: q 0..31 / h 0..79;  1: q 32..63 / h 72..151
    const int rb = (wid & 7) * 16;
    const int qoff = half * 32;
    const int jbO = half * 9;               // O j-range base
    const int r0 = rb + g, r1 = rb + g + 8;
    const int b = blockIdx.y, a0 = blockIdx.x * 128;
    const size_t base = (size_t)b * Lseq * 160;

    // stage Ah [128][160] -> stride 164
    #pragma unroll 2
    for (int t = 0; t < 10; t++) {
        int idx = tid + t*512;
        int r = idx / 40, c4 = idx - r*40;
        *(float4*)&Ahs[r*ST_A + c4*4] =
            *(const float4*)&g_Ah[base + (size_t)(a0 + r)*160 + c4*4];
    }

    float o[10][4];
    #pragma unroll
    for (int j = 0; j < 10; j++)
        #pragma unroll
        for (int e = 0; e < 4; e++) o[j][e] = 0.f;
    float m0 = -INFINITY, m1 = -INFINITY, l0 = 0.f, l1 = 0.f;

    for (int qt = 0; qt < 32; qt++) {
        const size_t qb = base + (size_t)qt * 64 * 160;
        #pragma unroll 2
        for (int t = 0; t < 5; t++) {
            int idx = tid + t*512;
            int q = idx / 40, c4 = idx - q*40;
            *(float4*)&Ps[q*ST_P + c4*4] = *(const float4*)&g_P [qb + (size_t)q*160 + c4*4];
            *(float4*)&Qs[q*ST_Q + c4*4] = *(const float4*)&g_Qh[qb + (size_t)q*160 + c4*4];
        }
        __syncthreads();

        // ---- S = Ah @ P^T : 16 rows x 32 q per warp, k = 152, 3x tf32 ----
        float s[4][4];
        #pragma unroll
        for (int j = 0; j < 4; j++)
            #pragma unroll
            for (int e = 0; e < 4; e++) s[j][e] = 0.f;
        #pragma unroll 1
        for (int t = 0; t < 19; t++) {
            int k0 = t*8;
            uint32_t ah[4], al[4];
            split32(Ahs[r0*ST_A + k0+tig  ], ah[0], al[0]);
            split32(Ahs[r1*ST_A + k0+tig  ], ah[1], al[1]);
            split32(Ahs[r0*ST_A + k0+tig+4], ah[2], al[2]);
            split32(Ahs[r1*ST_A + k0+tig+4], ah[3], al[3]);
            #pragma unroll
            for (int j = 0; j < 4; j++) {
                uint32_t bh0, bl0, bh1, bl1;
                split32(Ps[(qoff+8*j+g)*ST_P + k0+tig  ], bh0, bl0);
                split32(Ps[(qoff+8*j+g)*ST_P + k0+tig+4], bh1, bl1);
                mma8(s[j], ah[0], ah[1], ah[2], ah[3], bh0, bh1);
                mma8(s[j], ah[0], ah[1], ah[2], ah[3], bl0, bl1);
                mma8(s[j], al[0], al[1], al[2], al[3], bh0, bh1);
            }
        }

        // ---- partial row max over this warp's 32 q ----
        float mx0 = -INFINITY, mx1 = -INFINITY;
        #pragma unroll
        for (int j = 0; j < 4; j++) {
            mx0 = fmaxf(mx0, fmaxf(s[j][0], s[j][1]));
            mx1 = fmaxf(mx1, fmaxf(s[j][2], s[j][3]));
        }
        mx0 = fmaxf(mx0, __shfl_xor_sync(0xffffffffu, mx0, 1));
        mx0 = fmaxf(mx0, __shfl_xor_sync(0xffffffffu, mx0, 2));
        mx1 = fmaxf(mx1, __shfl_xor_sync(0xffffffffu, mx1, 1));
        mx1 = fmaxf(mx1, __shfl_xor_sync(0xffffffffu, mx1, 2));
        if (tig == 0) {
            pmax[half*128 + r0] = mx0;
            pmax[half*128 + r1] = mx1;
        }
        __syncthreads();

        // ---- combined new max; rescale O; E + partial sums ----
        float mn0 = fmaxf(m0, fmaxf(pmax[r0], pmax[128 + r0]));
        float mn1 = fmaxf(m1, fmaxf(pmax[r1], pmax[128 + r1]));
        float al0 = fexp(m0 - mn0), al1 = fexp(m1 - mn1);
        #pragma unroll
        for (int j = 0; j < 10; j++) {
            o[j][0] *= al0; o[j][1] *= al0;
            o[j][2] *= al1; o[j][3] *= al1;
        }
        float sum0 = 0.f, sum1 = 0.f;
        #pragma unroll
        for (int j = 0; j < 4; j++) {
            float e0 = fexp(s[j][0] - mn0);
            float e1 = fexp(s[j][1] - mn0);
            float e2 = fexp(s[j][2] - mn1);
            float e3 = fexp(s[j][3] - mn1);
            sum0 += e0 + e1; sum1 += e2 + e3;
            *(float2*)&Es[r0*ST_E + qoff + 8*j + 2*tig] = make_float2(e0, e1);
            *(float2*)&Es[r1*ST_E + qoff + 8*j + 2*tig] = make_float2(e2, e3);
        }
        sum0 += __shfl_xor_sync(0xffffffffu, sum0, 1);
        sum0 += __shfl_xor_sync(0xffffffffu, sum0, 2);
        sum1 += __shfl_xor_sync(0xffffffffu, sum1, 1);
        sum1 += __shfl_xor_sync(0xffffffffu, sum1, 2);
        if (tig == 0) {
            psum[half*128 + r0] = sum0;
            psum[half*128 + r1] = sum1;
        }
        __syncthreads();
        l0 = l0*al0 + psum[r0] + psum[128 + r0]; m0 = mn0;
        l1 = l1*al1 + psum[r1] + psum[128 + r1]; m1 = mn1;

        // ---- O += E @ Qh : 16 rows x 80 h per warp, k = 64, 3x tf32 ----
        #pragma unroll 1
        for (int t = 0; t < 8; t++) {
            int k0 = t*8;
            uint32_t eh[4], el[4];
            split32(Es[r0*ST_E + k0+tig  ], eh[0], el[0]);
            split32(Es[r1*ST_E + k0+tig  ], eh[1], el[1]);
            split32(Es[r0*ST_E + k0+tig+4], eh[2], el[2]);
            split32(Es[r1*ST_E + k0+tig+4], eh[3], el[3]);
            #pragma unroll
            for (int j = 0; j < 10; j++) {
                int jj = jbO + j;
                uint32_t bh0, bl0, bh1, bl1;
                split32(Qs[(k0+tig  )*ST_Q + 8*jj + g], bh0, bl0);
                split32(Qs[(k0+tig+4)*ST_Q + 8*jj + g], bh1, bl1);
                mma8(o[j], eh[0], eh[1], eh[2], eh[3], bh0, bh1);
                mma8(o[j], eh[0], eh[1], eh[2], eh[3], bl0, bl1);
                mma8(o[j], el[0], el[1], el[2], el[3], bh0, bh1);
            }
        }
        __syncthreads();   // Ps/Qs/Es free for next tile
    }

    // ---- normalize O into hm (overlay Ps/Qs) ----
    {
        float inv0 = 1.f / l0, inv1 = 1.f / l1;
        #pragma unroll
        for (int j = 0; j < 10; j++) {
            int c = 8*(jbO + j) + 2*tig;
            if (c < Hk) {
                *(float2*)&hm[r0*ST_H + c] = make_float2(o[j][0]*inv0, o[j][1]*inv0);
                *(float2*)&hm[r1*ST_H + c] = make_float2(o[j][2]*inv1, o[j][3]*inv1);
            }
        }
    }
    __syncthreads();

    // ---- epilogue: T = relu([Ah, Hm] @ Wt + bt), f32x2 SIMT ----
    {
        const int tx = tid & 15, tyy = tid >> 4;   // tyy 0..31
        u64t acc2[4][5];
        #pragma unroll
        for (int jp = 0; jp < 5; jp++) {
            int p = tx + 16*jp;
            u64t bb = (p < 75) ? *(const u64t*)&bt[2*p] : 0ull;
            #pragma unroll
            for (int i = 0; i < 4; i++) acc2[i][jp] = bb;
        }
        for (int h = 0; h < Hk; h++) {
            u64t avp[4];
            #pragma unroll
            for (int i = 0; i < 4; i++) {
                float a = Ahs[(tyy + 32*i)*ST_A + h];
                avp[i] = pack2(a, a);
            }
            #pragma unroll
            for (int jp = 0; jp < 5; jp++) {
                int p = tx + 16*jp;
                u64t w = (p < 75) ? *(const u64t*)&Wt[(size_t)h*Hk + 2*p] : 0ull;
                #pragma unroll
                for (int i = 0; i < 4; i++) ffma2(acc2[i][jp], avp[i], w);
            }
        }
        for (int h = 0; h < Hk; h++) {
            u64t ovp[4];
            #pragma unroll
            for (int i = 0; i < 4; i++) {
                float ov = hm[(tyy + 32*i)*ST_H + h];
                ovp[i] = pack2(ov, ov);
            }
            #pragma unroll
            for (int jp = 0; jp < 5; jp++) {
                int p = tx + 16*jp;
                u64t w = (p < 75) ? *(const u64t*)&Wt[(size_t)(Hk + h)*Hk + 2*p] : 0ull;
                #pragma unroll
                for (int i = 0; i < 4; i++) ffma2(acc2[i][jp], ovp[i], w);
            }
        }
        #pragma unroll
        for (int i = 0; i < 4; i++)
            #pragma unroll
            for (int jp = 0; jp < 5; jp++) {
                int p = tx + 16*jp;
                if (p < 75) {
                    int r = tyy + 32*i;
                    float v0 = fmaxf(lo_f(acc2[i][jp]), 0.f);
                    float v1 = fmaxf(hi_f(acc2[i][jp]), 0.f);
                    *(u64t*)&out[((size_t)b*Lseq + a0 + r)*Hk + 2*p] = pack2(v0, v1);
                }
            }
    }
}

// ---------------------------------------------------------------------------
extern "C" void kernel_launch(void* const* d_in, const int* in_sizes, int n_in,
                              void* d_out, int out_size)
{
    const float* Q  = (const float*)d_in[0];
    const float* A  = (const float*)d_in[1];
    const float* Wi = (const float*)d_in[2];
    const float* Wu = (const float*)d_in[3];
    const float* Wg = (const float*)d_in[4];
    const float* Wt = (const float*)d_in[5];
    const float* bi = (const float*)d_in[6];
    const float* bu = (const float*)d_in[7];
    const float* bg = (const float*)d_in[8];
    const float* bt = (const float*)d_in[9];
    float* out = (float*)d_out;

    cudaFuncSetAttribute(attn_kernel,
                         cudaFuncAttributeMaxDynamicSharedMemorySize,
                         SMF_TOT * (int)sizeof(float));

    gate_kernel<<<1024, 256>>>(Q, A, Wi, Wu, Wg, bi, bu, bg);
    attn_kernel<<<dim3(16, Bq), 512, SMF_TOT * sizeof(float)>>>(Wt, bt, out);
}

// round 16
// speedup vs baseline: 2.2480x; 1.0945x over previous
#include <cuda_runtime.h>
#include <math.h>
#include <stdint.h>

#define Bq   8
#define Lseq 2048
#define Dk   300
#define Hk   150
#define NROWS (Bq*Lseq)     // 16384

// scratch (allocation-free rule -> __device__ globals)
__device__ float g_Ah[(size_t)NROWS*160];          // [row][160], cols>=150 zero
__device__ float g_P [(size_t)NROWS*160];          // [row][160], cols>=150 zero
__device__ float g_Qt[(size_t)256*160*64];         // per 64-q-tile transposed [tile][h(160)][q(64)]

// ---------------- f32x2 helpers ----------------
typedef unsigned long long u64t;
__device__ __forceinline__ void ffma2(u64t &d, u64t a, u64t b) {
    asm("fma.rn.f32x2 %0, %1, %2, %0;" : "+l"(d) : "l"(a), "l"(b));
}
__device__ __forceinline__ float lo_f(u64t v){ return __uint_as_float((unsigned)v); }
__device__ __forceinline__ float hi_f(u64t v){ return __uint_as_float((unsigned)(v>>32)); }
__device__ __forceinline__ u64t pack2(float x, float y){
    u64t d; asm("mov.b64 %0, {%1,%2};" : "=l"(d)
                : "r"(__float_as_uint(x)), "r"(__float_as_uint(y))); return d;
}

// ---------------- bf16 mma helpers (plain mma.sync m16n8k16) ----------------
__device__ __forceinline__ void mma16(float* c, uint32_t a0, uint32_t a1,
                                      uint32_t a2, uint32_t a3,
                                      uint32_t b0, uint32_t b1) {
    asm volatile(
        "mma.sync.aligned.m16n8k16.row.col.f32.bf16.bf16.f32 "
        "{%0,%1,%2,%3}, {%4,%5,%6,%7}, {%8,%9}, {%0,%1,%2,%3};"
        : "+f"(c[0]), "+f"(c[1]), "+f"(c[2]), "+f"(c[3])
        : "r"(a0), "r"(a1), "r"(a2), "r"(a3), "r"(b0), "r"(b1));
}
// 2-term bf16 split of a float pair: h = bf16x2(x0,x1), l = bf16x2(residuals)
__device__ __forceinline__ void splitb2(float x0, float x1, uint32_t &h, uint32_t &l) {
    uint32_t hh;
    asm("cvt.rn.bf16x2.f32 %0, %1, %2;" : "=r"(hh) : "f"(x1), "f"(x0));
    float h0 = __uint_as_float(hh << 16);
    float h1 = __uint_as_float(hh & 0xffff0000u);
    uint32_t ll;
    asm("cvt.rn.bf16x2.f32 %0, %1, %2;" : "=r"(ll) : "f"(x1 - h1), "f"(x0 - h0));
    h = hh; l = ll;
}

// fast exp via FMA-pipe polynomial; x <= 0 expected
__device__ __forceinline__ float fexp(float x) {
    float y = fmaxf(x * 1.4426950408889634f, -126.0f);
    int   ii = __float2int_rn(y);
    float f = y - (float)ii;
    float p = 0.0013333558f;
    p = p*f + 0.009618129f;
    p = p*f + 0.055504109f;
    p = p*f + 0.24022651f;
    p = p*f + 0.69314718f;
    p = p*f + 1.0f;
    return __int_as_float((ii + 127) << 23) * p;
}

// ---------------------------------------------------------------------------
// Kernel 1: gated projection (f32x2 over n-pairs); Q blocks fuse P = Qh@Wg+bg
// and store Qh TRANSPOSED per 64-q-tile into g_Qt.
// ---------------------------------------------------------------------------
__global__ __launch_bounds__(256) void gate_kernel(
    const float* __restrict__ Q, const float* __restrict__ A,
    const float* __restrict__ Wi, const float* __restrict__ Wu,
    const float* __restrict__ Wg,
    const float* __restrict__ bi, const float* __restrict__ bu,
    const float* __restrict__ bg)
{
    __shared__ float sm[10560];
    float* Xs  = sm;          // [32][30]
    float* Wis = sm + 960;    // [30][160]
    float* Wus = sm + 5760;   // [30][160]
    float* Qhs = sm;          // [32][160] (P phase)
    float* Wgs = sm + 5760;   // [30][160] (P phase)

    const int tid = threadIdx.x;
    const int tx = tid & 15, ty = tid >> 4;
    const bool isQ = (blockIdx.x < 512);
    const int row0 = (blockIdx.x & 511) * 32;
    const float* X = isQ ? Q : A;

    u64t ai2[2][5], au2[2][5];
    #pragma unroll
    for (int i = 0; i < 2; i++)
        #pragma unroll
        for (int jp = 0; jp < 5; jp++) { ai2[i][jp] = 0ull; au2[i][jp] = 0ull; }

    for (int kt = 0; kt < 10; kt++) {
        for (int idx = tid; idx < 32*30; idx += 256) {
            int m = idx / 30, kk = idx - m*30;
            Xs[idx] = X[(size_t)(row0 + m) * Dk + kt*30 + kk];
        }
        for (int idx = tid; idx < 30*160; idx += 256) {
            int kk = idx / 160, n = idx - kk*160;
            float wi = 0.f, wu = 0.f;
            if (n < Hk) { int g = (kt*30 + kk) * Hk + n; wi = Wi[g]; wu = Wu[g]; }
            Wis[idx] = wi; Wus[idx] = wu;
        }
        __syncthreads();
        #pragma unroll 5
        for (int k = 0; k < 30; k++) {
            float x0 = Xs[(ty*2    )*30 + k];
            float x1 = Xs[(ty*2 + 1)*30 + k];
            u64t x0p = pack2(x0, x0), x1p = pack2(x1, x1);
            #pragma unroll
            for (int jp = 0; jp < 5; jp++) {
                u64t wi = *(const u64t*)&Wis[k*160 + 2*(tx + 16*jp)];
                u64t wu = *(const u64t*)&Wus[k*160 + 2*(tx + 16*jp)];
                ffma2(ai2[0][jp], x0p, wi); ffma2(ai2[1][jp], x1p, wi);
                ffma2(au2[0][jp], x0p, wu); ffma2(au2[1][jp], x1p, wu);
            }
        }
        __syncthreads();
    }

    // nonlinearity
    float hv[2][10];
    #pragma unroll
    for (int i = 0; i < 2; i++)
        #pragma unroll
        for (int jp = 0; jp < 5; jp++) {
            int n0 = 2*(tx + 16*jp);
            bool v = (n0 < Hk);
            float bi0 = v ? bi[n0] : 0.f, bi1 = v ? bi[n0+1] : 0.f;
            float bu0 = v ? bu[n0] : 0.f, bu1 = v ? bu[n0+1] : 0.f;
            float s0 = 1.f/(1.f + __expf(-(lo_f(ai2[i][jp]) + bi0)));
            float s1 = 1.f/(1.f + __expf(-(hi_f(ai2[i][jp]) + bi1)));
            float h0 = s0 * tanhf(lo_f(au2[i][jp]) + bu0);
            float h1 = s1 * tanhf(hi_f(au2[i][jp]) + bu1);
            hv[i][jp*2]   = v ? h0 : 0.f;
            hv[i][jp*2+1] = v ? h1 : 0.f;
        }

    if (!isQ) {
        #pragma unroll
        for (int i = 0; i < 2; i++)
            #pragma unroll
            for (int jp = 0; jp < 5; jp++) {
                int n0 = 2*(tx + 16*jp);
                *(u64t*)&g_Ah[(size_t)(row0 + ty*2 + i)*160 + n0] =
                    pack2(hv[i][jp*2], hv[i][jp*2+1]);
            }
        return;
    }

    // transposed Qh store: g_Qt[t64][h][q], plus zero rows 150..159
    {
        int t64 = row0 >> 6, qb = row0 & 63;
        size_t tb = (size_t)t64 * 160 * 64;
        #pragma unroll
        for (int i = 0; i < 2; i++)
            #pragma unroll
            for (int jp = 0; jp < 5; jp++) {
                int n0 = 2*(tx + 16*jp);
                if (n0 < Hk) {
                    g_Qt[tb + (size_t)n0*64     + qb + ty*2 + i] = hv[i][jp*2];
                    g_Qt[tb + (size_t)(n0+1)*64 + qb + ty*2 + i] = hv[i][jp*2+1];
                }
            }
        for (int idx = tid; idx < 10*32; idx += 256) {
            int h = 150 + (idx >> 5), q = qb + (idx & 31);
            g_Qt[tb + (size_t)h*64 + q] = 0.f;
        }
    }

    // P = Qh @ Wg + bg
    __syncthreads();
    #pragma unroll
    for (int i = 0; i < 2; i++)
        #pragma unroll
        for (int jp = 0; jp < 5; jp++) {
            int n0 = 2*(tx + 16*jp);
            *(u64t*)&Qhs[(ty*2 + i)*160 + n0] = pack2(hv[i][jp*2], hv[i][jp*2+1]);
        }
    __syncthreads();

    u64t ap2[2][5];
    #pragma unroll
    for (int i = 0; i < 2; i++)
        #pragma unroll
        for (int jp = 0; jp < 5; jp++) ap2[i][jp] = 0ull;

    for (int kt = 0; kt < 5; kt++) {
        for (int idx = tid; idx < 30*160; idx += 256) {
            int kk = idx / 160, n = idx - kk*160;
            Wgs[idx] = (n < Hk) ? Wg[(kt*30 + kk) * Hk + n] : 0.f;
        }
        __syncthreads();
        #pragma unroll 5
        for (int k = 0; k < 30; k++) {
            float q0 = Qhs[(ty*2    )*160 + kt*30 + k];
            float q1 = Qhs[(ty*2 + 1)*160 + kt*30 + k];
            u64t q0p = pack2(q0, q0), q1p = pack2(q1, q1);
            #pragma unroll
            for (int jp = 0; jp < 5; jp++) {
                u64t wg = *(const u64t*)&Wgs[k*160 + 2*(tx + 16*jp)];
                ffma2(ap2[0][jp], q0p, wg);
                ffma2(ap2[1][jp], q1p, wg);
            }
        }
        __syncthreads();
    }
    #pragma unroll
    for (int i = 0; i < 2; i++)
        #pragma unroll
        for (int jp = 0; jp < 5; jp++) {
            int n0 = 2*(tx + 16*jp);
            bool v = (n0 < Hk);
            float p0 = v ? lo_f(ap2[i][jp]) + bg[n0]   : 0.f;
            float p1 = v ? hi_f(ap2[i][jp]) + bg[n0+1] : 0.f;
            *(u64t*)&g_P[(size_t)(row0 + ty*2 + i)*160 + n0] = pack2(p0, p1);
        }
}

// ---------------------------------------------------------------------------
// Kernel 2: one-pass flash attention, bf16 m16n8k16 2-term split, 512 threads.
// Warp pair (w, w+8): S split along q (32 each), O split along h (j 0..9/9..18).
// ---------------------------------------------------------------------------
#define ST_A  164
#define ST_P  164
#define ST_QT 68
#define ST_E  68
#define ST_H  154
#define OFF_P   (128*ST_A)                     // 20992
#define OFF_QT  (OFF_P + 64*ST_P)              // 31488
#define OFF_E   (OFF_QT + 160*ST_QT)           // 42368
#define OFF_PM  (OFF_E + 128*ST_E)             // 51072
#define OFF_PS  (OFF_PM + 256)                 // 51328
#define SMF_TOT (OFF_PS + 256)                 // 51584 floats = 206336 B

__global__ __launch_bounds__(512, 1) void attn_kernel(
    const float* __restrict__ Wt, const float* __restrict__ bt,
    float* __restrict__ out)
{
    extern __shared__ __align__(16) float sm[];
    float* Ahs  = sm;
    float* Ps   = sm + OFF_P;
    float* Qts  = sm + OFF_QT;
    float* Es   = sm + OFF_E;
    float* pmax = sm + OFF_PM;   // [2][128]
    float* psum = sm + OFF_PS;   // [2][128]
    float* hm   = sm + OFF_P;    // overlay after main loop

    const int tid = threadIdx.x;
    const int wid = tid >> 5, lane = tid & 31;
    const int g = lane >> 2, tig = lane & 3;
    const int half = wid >> 3;
    const int rb = (wid & 7) * 16;
    const int qoff = half * 32;
    const int jbO = half * 9;
    const int r0 = rb + g, r1 = rb + g + 8;
    const int b = blockIdx.y, a0 = blockIdx.x * 128;
    const size_t base = (size_t)b * Lseq * 160;

    // stage Ah [128][160] -> stride 164
    #pragma unroll 2
    for (int t = 0; t < 10; t++) {
        int idx = tid + t*512;
        int r = idx / 40, c4 = idx - r*40;
        *(float4*)&Ahs[r*ST_A + c4*4] =
            *(const float4*)&g_Ah[base + (size_t)(a0 + r)*160 + c4*4];
    }

    float o[10][4];
    #pragma unroll
    for (int j = 0; j < 10; j++)
        #pragma unroll
        for (int e = 0; e < 4; e++) o[j][e] = 0.f;
    float m0 = -INFINITY, m1 = -INFINITY, l0 = 0.f, l1 = 0.f;

    for (int qt = 0; qt < 32; qt++) {
        const size_t qb = base + (size_t)qt * 64 * 160;
        const size_t qtb = (size_t)(b*32 + qt) * 160 * 64;
        #pragma unroll
        for (int t = 0; t < 5; t++) {
            int idx = tid + t*512;
            int q = idx / 40, c4 = idx - q*40;
            *(float4*)&Ps[q*ST_P + c4*4] =
                *(const float4*)&g_P[qb + (size_t)q*160 + c4*4];
        }
        #pragma unroll
        for (int t = 0; t < 5; t++) {
            int idx = tid + t*512;
            int h = idx >> 4, c4 = idx & 15;
            *(float4*)&Qts[h*ST_QT + c4*4] =
                *(const float4*)&g_Qt[qtb + (size_t)h*64 + c4*4];
        }
        __syncthreads();

        // ---- S = Ah @ P^T : 16 rows x 32 q per warp, K=160 (10 chunks), bf16 2-term ----
        float s[4][4];
        #pragma unroll
        for (int j = 0; j < 4; j++)
            #pragma unroll
            for (int e = 0; e < 4; e++) s[j][e] = 0.f;
        #pragma unroll 1
        for (int t = 0; t < 10; t++) {
            int k0 = t*16;
            float2 aA = *(const float2*)&Ahs[r0*ST_A + k0 + 2*tig];
            float2 aB = *(const float2*)&Ahs[r1*ST_A + k0 + 2*tig];
            float2 aC = *(const float2*)&Ahs[r0*ST_A + k0 + 8 + 2*tig];
            float2 aD = *(const float2*)&Ahs[r1*ST_A + k0 + 8 + 2*tig];
            uint32_t ah0,al0,ah1,al1,ah2,al2,ah3,al3;
            splitb2(aA.x, aA.y, ah0, al0);
            splitb2(aB.x, aB.y, ah1, al1);
            splitb2(aC.x, aC.y, ah2, al2);
            splitb2(aD.x, aD.y, ah3, al3);
            #pragma unroll
            for (int j = 0; j < 4; j++) {
                int q = qoff + 8*j + g;
                float2 b0f = *(const float2*)&Ps[q*ST_P + k0 + 2*tig];
                float2 b1f = *(const float2*)&Ps[q*ST_P + k0 + 8 + 2*tig];
                uint32_t bh0,bl0,bh1,bl1;
                splitb2(b0f.x, b0f.y, bh0, bl0);
                splitb2(b1f.x, b1f.y, bh1, bl1);
                mma16(s[j], ah0,ah1,ah2,ah3, bh0,bh1);
                mma16(s[j], ah0,ah1,ah2,ah3, bl0,bl1);
                mma16(s[j], al0,al1,al2,al3, bh0,bh1);
            }
        }

        // ---- partial row max over this warp's 32 q ----
        float mx0 = -INFINITY, mx1 = -INFINITY;
        #pragma unroll
        for (int j = 0; j < 4; j++) {
            mx0 = fmaxf(mx0, fmaxf(s[j][0], s[j][1]));
            mx1 = fmaxf(mx1, fmaxf(s[j][2], s[j][3]));
        }
        mx0 = fmaxf(mx0, __shfl_xor_sync(0xffffffffu, mx0, 1));
        mx0 = fmaxf(mx0, __shfl_xor_sync(0xffffffffu, mx0, 2));
        mx1 = fmaxf(mx1, __shfl_xor_sync(0xffffffffu, mx1, 1));
        mx1 = fmaxf(mx1, __shfl_xor_sync(0xffffffffu, mx1, 2));
        if (tig == 0) {
            pmax[half*128 + r0] = mx0;
            pmax[half*128 + r1] = mx1;
        }
        __syncthreads();

        // ---- combined new max; rescale O; E + partial sums ----
        float mn0 = fmaxf(m0, fmaxf(pmax[r0], pmax[128 + r0]));
        float mn1 = fmaxf(m1, fmaxf(pmax[r1], pmax[128 + r1]));
        float al0 = fexp(m0 - mn0), al1 = fexp(m1 - mn1);
        #pragma unroll
        for (int j = 0; j < 10; j++) {
            o[j][0] *= al0; o[j][1] *= al0;
            o[j][2] *= al1; o[j][3] *= al1;
        }
        float sum0 = 0.f, sum1 = 0.f;
        #pragma unroll
        for (int j = 0; j < 4; j++) {
            float e0 = fexp(s[j][0] - mn0);
            float e1 = fexp(s[j][1] - mn0);
            float e2 = fexp(s[j][2] - mn1);
            float e3 = fexp(s[j][3] - mn1);
            sum0 += e0 + e1; sum1 += e2 + e3;
            *(float2*)&Es[r0*ST_E + qoff + 8*j + 2*tig] = make_float2(e0, e1);
            *(float2*)&Es[r1*ST_E + qoff + 8*j + 2*tig] = make_float2(e2, e3);
        }
        sum0 += __shfl_xor_sync(0xffffffffu, sum0, 1);
        sum0 += __shfl_xor_sync(0xffffffffu, sum0, 2);
        sum1 += __shfl_xor_sync(0xffffffffu, sum1, 1);
        sum1 += __shfl_xor_sync(0xffffffffu, sum1, 2);
        if (tig == 0) {
            psum[half*128 + r0] = sum0;
            psum[half*128 + r1] = sum1;
        }
        __syncthreads();
        l0 = l0*al0 + psum[r0] + psum[128 + r0]; m0 = mn0;
        l1 = l1*al1 + psum[r1] + psum[128 + r1]; m1 = mn1;

        // ---- O += E @ Qh : 16 rows x 80 h per warp, K=64 (4 chunks), bf16 2-term ----
        #pragma unroll 1
        for (int t = 0; t < 4; t++) {
            int k0 = t*16;
            float2 eA = *(const float2*)&Es[r0*ST_E + k0 + 2*tig];
            float2 eB = *(const float2*)&Es[r1*ST_E + k0 + 2*tig];
            float2 eC = *(const float2*)&Es[r0*ST_E + k0 + 8 + 2*tig];
            float2 eD = *(const float2*)&Es[r1*ST_E + k0 + 8 + 2*tig];
            uint32_t eh0,el0,eh1,el1,eh2,el2,eh3,el3;
            splitb2(eA.x, eA.y, eh0, el0);
            splitb2(eB.x, eB.y, eh1, el1);
            splitb2(eC.x, eC.y, eh2, el2);
            splitb2(eD.x, eD.y, eh3, el3);
            #pragma unroll
            for (int j = 0; j < 10; j++) {
                int col = 8*(jbO + j) + g;
                float2 q0f = *(const float2*)&Qts[col*ST_QT + k0 + 2*tig];
                float2 q1f = *(const float2*)&Qts[col*ST_QT + k0 + 8 + 2*tig];
                uint32_t qh0,ql0,qh1,ql1;
                splitb2(q0f.x, q0f.y, qh0, ql0);
                splitb2(q1f.x, q1f.y, qh1, ql1);
                mma16(o[j], eh0,eh1,eh2,eh3, qh0,qh1);
                mma16(o[j], eh0,eh1,eh2,eh3, ql0,ql1);
                mma16(o[j], el0,el1,el2,el3, qh0,qh1);
            }
        }
        __syncthreads();   // Ps/Qts/Es free for next tile
    }

    // ---- normalize O into hm (overlay Ps/Qts) ----
    {
        float inv0 = 1.f / l0, inv1 = 1.f / l1;
        #pragma unroll
        for (int j = 0; j < 10; j++) {
            int c = 8*(jbO + j) + 2*tig;
            if (c < Hk) {
                *(float2*)&hm[r0*ST_H + c] = make_float2(o[j][0]*inv0, o[j][1]*inv0);
                *(float2*)&hm[r1*ST_H + c] = make_float2(o[j][2]*inv1, o[j][3]*inv1);
            }
        }
    }
    __syncthreads();

    // ---- epilogue: T = relu([Ah, Hm] @ Wt + bt), f32x2 SIMT ----
    {
        const int tx = tid & 15, tyy = tid >> 4;   // tyy 0..31
        u64t acc2[4][5];
        #pragma unroll
        for (int jp = 0; jp < 5; jp++) {
            int p = tx + 16*jp;
            u64t bb = (p < 75) ? *(const u64t*)&bt[2*p] : 0ull;
            #pragma unroll
            for (int i = 0; i < 4; i++) acc2[i][jp] = bb;
        }
        for (int h = 0; h < Hk; h++) {
            u64t avp[4];
            #pragma unroll
            for (int i = 0; i < 4; i++) {
                float a = Ahs[(tyy + 32*i)*ST_A + h];
                avp[i] = pack2(a, a);
            }
            #pragma unroll
            for (int jp = 0; jp < 5; jp++) {
                int p = tx + 16*jp;
                u64t w = (p < 75) ? *(const u64t*)&Wt[(size_t)h*Hk + 2*p] : 0ull;
                #pragma unroll
                for (int i = 0; i < 4; i++) ffma2(acc2[i][jp], avp[i], w);
            }
        }
        for (int h = 0; h < Hk; h++) {
            u64t ovp[4];
            #pragma unroll
            for (int i = 0; i < 4; i++) {
                float ov = hm[(tyy + 32*i)*ST_H + h];
                ovp[i] = pack2(ov, ov);
            }
            #pragma unroll
            for (int jp = 0; jp < 5; jp++) {
                int p = tx + 16*jp;
                u64t w = (p < 75) ? *(const u64t*)&Wt[(size_t)(Hk + h)*Hk + 2*p] : 0ull;
                #pragma unroll
                for (int i = 0; i < 4; i++) ffma2(acc2[i][jp], ovp[i], w);
            }
        }
        #pragma unroll
        for (int i = 0; i < 4; i++)
            #pragma unroll
            for (int jp = 0; jp < 5; jp++) {
                int p = tx + 16*jp;
                if (p < 75) {
                    int r = tyy + 32*i;
                    float v0 = fmaxf(lo_f(acc2[i][jp]), 0.f);
                    float v1 = fmaxf(hi_f(acc2[i][jp]), 0.f);
                    *(u64t*)&out[((size_t)b*Lseq + a0 + r)*Hk + 2*p] = pack2(v0, v1);
                }
            }
    }
}

// ---------------------------------------------------------------------------
extern "C" void kernel_launch(void* const* d_in, const int* in_sizes, int n_in,
                              void* d_out, int out_size)
{
    const float* Q  = (const float*)d_in[0];
    const float* A  = (const float*)d_in[1];
    const float* Wi = (const float*)d_in[2];
    const float* Wu = (const float*)d_in[3];
    const float* Wg = (const float*)d_in[4];
    const float* Wt = (const float*)d_in[5];
    const float* bi = (const float*)d_in[6];
    const float* bu = (const float*)d_in[7];
    const float* bg = (const float*)d_in[8];
    const float* bt = (const float*)d_in[9];
    float* out = (float*)d_out;

    cudaFuncSetAttribute(attn_kernel,
                         cudaFuncAttributeMaxDynamicSharedMemorySize,
                         SMF_TOT * (int)sizeof(float));

    gate_kernel<<<1024, 256>>>(Q, A, Wi, Wu, Wg, bi, bu, bg);
    attn_kernel<<<dim3(16, Bq), 512, SMF_TOT * sizeof(float)>>>(Wt, bt, out);
}